// round 8
// baseline (speedup 1.0000x reference)
#include <cuda_runtime.h>
#include <math.h>

// Problem constants
#define B_   32
#define H_   256
#define W_   1216
#define SH_  16
#define SW_  48
#define KH_  30     // int(2*256/17)
#define KW_  49     // int(2*1216/49)
#define HP_  227    // 256-30+1  (valid conv out H)
#define WP_  1168   // 1216-49+1 (valid conv out W)

#define N_SPARSE (B_*H_*W_)               // 9,961,472
#define N_DVT    (B_*H_*W_*2)             // 19,922,944
#define OUT_DVT_OFF   N_SPARSE
#define OUT_GRID_OFF  (N_SPARSE + N_DVT)  // 29,884,416

struct K30 { float v[KH_]; };
struct K49 { float v[KW_]; };

// ---------------------------------------------------------------------------
// ONE kernel, ONE wave. Block = (i:16, b:32), 256 threads, 4 blocks/SM
// => 1024 threads/SM => 64 regs/thread (MLP headroom), n_conc=592 >= 512.
// Block (b,i) owns sparse rows / dvt rows [16i,16i+16) of batch b and
// sample row i. Scatter row is 16i+8 +- ~1 => no inter-block races.
// Phase order: vconv reads the 30-row window first; transpose then re-reads
// 16 of those rows from L2 (saves ~35 MB DRAM).
// ---------------------------------------------------------------------------
__global__ void __launch_bounds__(256, 4)
k_mega(const float4* __restrict__ dvf4,
       const float* __restrict__ gt,
       float* __restrict__ out,
       K30 GH, K49 GW) {
    int i = blockIdx.x;   // sample row / slice index 0..15
    int b = blockIdx.y;   // batch
    int t = threadIdx.x;  // 0..255

    __shared__ float row[2][W_];

    // ---- vertical Gaussian pass: 30-tap dot per (ch,w4) column task ------
    // 608 tasks over 256 threads (threads 0..95 do 3, rest do 2).
    {
        int h0 = (i * HP_) >> 4;   // i*227/16
#pragma unroll 1
        for (int task = t; task < 608; task += 256) {
            int ch = task >= 304;
            int w4 = ch ? (task - 304) : task;
            const float4* src = dvf4 + (((size_t)(b * 2 + ch) * H_) + h0) * 304 + w4;
            float4 acc = make_float4(0.f, 0.f, 0.f, 0.f);
#pragma unroll
            for (int r = 0; r < KH_; r++) {
                float4 v = src[r * 304];
                float  w = GH.v[r];
                acc.x += w * v.x; acc.y += w * v.y; acc.z += w * v.z; acc.w += w * v.w;
            }
            *reinterpret_cast<float4*>(&row[ch][4 * w4]) = acc;
        }
    }

    // ---- transpose slice: dvf [b][c][16i+r][:] -> dvt [b][16i+r][:][c] ---
    // 16 rows x 304 float4-pairs = 4864 tasks = 256 threads x 19 iters.
    // float4 loads batched 2-wide: 4 x 16B independent loads in flight.
    {
        const float4* c0 = dvf4 + (((size_t)(b * 2 + 0) * H_) + 16 * i) * 304;
        const float4* c1 = dvf4 + (((size_t)(b * 2 + 1) * H_) + 16 * i) * 304;
        float4* dst = reinterpret_cast<float4*>(out + OUT_DVT_OFF)
                      + (((size_t)b * H_) + 16 * i) * 608;
        int idx = t;
#pragma unroll 1
        for (int rep = 0; rep < 9; rep++) {    // 9 reps x 2 = 18 iters
            float4 a0 = c0[idx];         float4 q0 = c1[idx];
            float4 a1 = c0[idx + 256];   float4 q1 = c1[idx + 256];
            __stcs(&dst[2 * idx + 0],   make_float4(a0.x, q0.x, a0.y, q0.y));
            __stcs(&dst[2 * idx + 1],   make_float4(a0.z, q0.z, a0.w, q0.w));
            __stcs(&dst[2 * (idx + 256) + 0], make_float4(a1.x, q1.x, a1.y, q1.y));
            __stcs(&dst[2 * (idx + 256) + 1], make_float4(a1.z, q1.z, a1.w, q1.w));
            idx += 512;
        }
        {   // remainder: 19th iter; idx = t + 4608
            float4 a0 = c0[idx];         float4 q0 = c1[idx];
            __stcs(&dst[2 * idx + 0], make_float4(a0.x, q0.x, a0.y, q0.y));
            __stcs(&dst[2 * idx + 1], make_float4(a0.z, q0.z, a0.w, q0.w));
        }
    }

    // ---- zero owned sparse rows: 16 rows x 304 float4 = 4864 float4 ------
    {
        float4* z = reinterpret_cast<float4*>(out)
                    + (((size_t)b * H_) + 16 * i) * 304;
        const float4 zero4 = make_float4(0.f, 0.f, 0.f, 0.f);
#pragma unroll 1
        for (int k = t; k < 4864; k += 256) __stcs(&z[k], zero4);
    }

    __syncthreads();

    // ---- horizontal pass + epilogue: one thread per sample column j ------
    if (t < SW_) {
        int j = t;
        int w0 = (j * WP_) / SW_;
        float ax = 0.f, ay = 0.f;
#pragma unroll
        for (int s = 0; s < KW_; s++) {
            float w = GW.v[s];
            ax += w * row[0][w0 + s];
            ay += w * row[1][w0 + s];
        }
        float gx = ax + (2.0f * (float)j - 47.0f) * (1.0f / 48.0f);
        float gy = ay + (2.0f * (float)i - 15.0f) * (1.0f / 16.0f);
        reinterpret_cast<float2*>(out + OUT_GRID_OFF)[(b * SH_ + i) * SW_ + j]
            = make_float2(gx, gy);

        // bilinear grid_sample (zeros padding, align_corners=False)
        float x = (gx + 1.0f) * ((float)W_ * 0.5f) - 0.5f;
        float y = (gy + 1.0f) * ((float)H_ * 0.5f) - 0.5f;
        float x0f = floorf(x), y0f = floorf(y);
        int x0 = (int)x0f, y0 = (int)y0f;
        int x1 = x0 + 1,   y1 = y0 + 1;
        float wx1 = x - x0f, wx0 = 1.0f - wx1;
        float wy1 = y - y0f, wy0 = 1.0f - wy1;

        const float* gtb = gt + (size_t)b * (H_ * W_);
        float v00 = 0.f, v01 = 0.f, v10 = 0.f, v11 = 0.f;
        bool yok0 = (y0 >= 0) && (y0 < H_);
        bool yok1 = (y1 >= 0) && (y1 < H_);
        bool xok0 = (x0 >= 0) && (x0 < W_);
        bool xok1 = (x1 >= 0) && (x1 < W_);
        if (yok0 && xok0) v00 = gtb[y0 * W_ + x0];
        if (yok0 && xok1) v01 = gtb[y0 * W_ + x1];
        if (yok1 && xok0) v10 = gtb[y1 * W_ + x0];
        if (yok1 && xok1) v11 = gtb[y1 * W_ + x1];
        float val = wy0 * wx0 * v00 + wy0 * wx1 * v01
                  + wy1 * wx0 * v10 + wy1 * wx1 * v11;

        // scatter (truncation matches astype(int32) after the clip)
        float rf = (gy + 1.0f) * 0.5f * (float)H_;
        float cf = (gx + 1.0f) * 0.5f * (float)W_;
        int rI = (int)rf;  rI = rI < 0 ? 0 : (rI > H_ - 1 ? H_ - 1 : rI);
        int cI = (int)cf;  cI = cI < 0 ? 0 : (cI > W_ - 1 ? W_ - 1 : cI);
        if (rI >= 96) out[((size_t)b * H_ + rI) * W_ + cI] = val;
    }
}

// ---------------------------------------------------------------------------
extern "C" void kernel_launch(void* const* d_in, const int* in_sizes, int n_in,
                              void* d_out, int out_size) {
    const float* gt  = (const float*)d_in[0];
    const float* dvf = (const float*)d_in[1];
    float* out = (float*)d_out;

    // Gaussian weights in double, normalized per-axis (separable equivalent of
    // k = outer(gh,gw)/k.sum()).
    K30 GH; K49 GW;
    {
        double sh = (2.0 * (double)H_ / (double)(SH_ + 1)) / 3.0;  // 512/17/3
        double sw = (2.0 * (double)W_ / (double)(SW_ + 1)) / 3.0;  // 2432/49/3
        double g[KW_], s;
        s = 0.0;
        for (int r = 0; r < KH_; r++) {
            double u = ((double)r - (double)(KH_ - 1) / 2.0) / sh;
            g[r] = exp(-u * u / 2.0);
            s += g[r];
        }
        for (int r = 0; r < KH_; r++) GH.v[r] = (float)(g[r] / s);
        s = 0.0;
        for (int c = 0; c < KW_; c++) {
            double u = ((double)c - (double)(KW_ - 1) / 2.0) / sw;
            g[c] = exp(-u * u / 2.0);
            s += g[c];
        }
        for (int c = 0; c < KW_; c++) GW.v[c] = (float)(g[c] / s);
    }

    k_mega<<<dim3(SH_, B_), 256>>>((const float4*)dvf, gt, out, GH, GW);
}

// round 9
// speedup vs baseline: 1.0622x; 1.0622x over previous
#include <cuda_runtime.h>
#include <math.h>

// Problem constants
#define B_   32
#define H_   256
#define W_   1216
#define SH_  16
#define SW_  48
#define KH_  30     // int(2*256/17)
#define KW_  49     // int(2*1216/49)
#define HP_  227    // 256-30+1  (valid conv out H)
#define WP_  1168   // 1216-49+1 (valid conv out W)

#define N_SPARSE (B_*H_*W_)               // 9,961,472
#define N_DVT    (B_*H_*W_*2)             // 19,922,944
#define OUT_DVT_OFF   N_SPARSE
#define OUT_GRID_OFF  (N_SPARSE + N_DVT)  // 29,884,416

#define NR1 512          // role-1: vconv+epilogue+scatter-zone zero, (b,i)
#define NR2 2048         // role-2: transpose, 4 rows per block
#define NR3 512          // role-3: zero remaining 8 rows per slice
#define GRID_TOTAL (NR1 + NR2 + NR3)

struct K30 { float v[KH_]; };
struct K49 { float v[KW_]; };

// ---------------------------------------------------------------------------
// One launch, three block roles. Fine-grained blocks => scheduler backfill
// hides per-block spread (one-wave design left SMs idle on the straggler
// tail). Role-1 zeroes ONLY rows [16i+4,16i+12) before scattering into
// 16i+8 +- 2 (>>6 sigma margin); role-3 zeroes the complementary rows.
// ---------------------------------------------------------------------------
__global__ void __launch_bounds__(256, 8)
k_mega(const float4* __restrict__ dvf4,
       const float* __restrict__ gt,
       float* __restrict__ out,
       K30 GH, K49 GW) {
    int bid = blockIdx.x;
    int t = threadIdx.x;  // 0..255

    if (bid < NR1) {
        // ================= role 1: sample pipeline =========================
        int b = bid >> 4;
        int i = bid & 15;
        __shared__ float row[2][W_];

        // vertical Gaussian pass: 608 (ch,w4) tasks over 256 threads
        int h0 = (i * HP_) >> 4;   // i*227/16
#pragma unroll 1
        for (int task = t; task < 608; task += 256) {
            int ch = task >= 304;
            int w4 = ch ? (task - 304) : task;
            const float4* src = dvf4 + (((size_t)(b * 2 + ch) * H_) + h0) * 304 + w4;
            float4 acc = make_float4(0.f, 0.f, 0.f, 0.f);
#pragma unroll
            for (int r = 0; r < KH_; r++) {
                float4 v = src[r * 304];
                float  w = GH.v[r];
                acc.x += w * v.x; acc.y += w * v.y; acc.z += w * v.z; acc.w += w * v.w;
            }
            *reinterpret_cast<float4*>(&row[ch][4 * w4]) = acc;
        }

        // zero the scatter zone: rows [16i+4, 16i+12) = 8 x 304 float4
        {
            float4* z = reinterpret_cast<float4*>(out)
                        + (((size_t)b * H_) + 16 * i + 4) * 304;
            const float4 zero4 = make_float4(0.f, 0.f, 0.f, 0.f);
#pragma unroll 1
            for (int k = t; k < 8 * 304; k += 256) __stcs(&z[k], zero4);
        }

        __syncthreads();

        // horizontal pass + grid write + bilinear sample + scatter
        if (t < SW_) {
            int j = t;
            int w0 = (j * WP_) / SW_;
            float ax = 0.f, ay = 0.f;
#pragma unroll
            for (int s = 0; s < KW_; s++) {
                float w = GW.v[s];
                ax += w * row[0][w0 + s];
                ay += w * row[1][w0 + s];
            }
            float gx = ax + (2.0f * (float)j - 47.0f) * (1.0f / 48.0f);
            float gy = ay + (2.0f * (float)i - 15.0f) * (1.0f / 16.0f);
            reinterpret_cast<float2*>(out + OUT_GRID_OFF)[(b * SH_ + i) * SW_ + j]
                = make_float2(gx, gy);

            // bilinear grid_sample (zeros padding, align_corners=False)
            float x = (gx + 1.0f) * ((float)W_ * 0.5f) - 0.5f;
            float y = (gy + 1.0f) * ((float)H_ * 0.5f) - 0.5f;
            float x0f = floorf(x), y0f = floorf(y);
            int x0 = (int)x0f, y0 = (int)y0f;
            int x1 = x0 + 1,   y1 = y0 + 1;
            float wx1 = x - x0f, wx0 = 1.0f - wx1;
            float wy1 = y - y0f, wy0 = 1.0f - wy1;

            const float* gtb = gt + (size_t)b * (H_ * W_);
            float v00 = 0.f, v01 = 0.f, v10 = 0.f, v11 = 0.f;
            bool yok0 = (y0 >= 0) && (y0 < H_);
            bool yok1 = (y1 >= 0) && (y1 < H_);
            bool xok0 = (x0 >= 0) && (x0 < W_);
            bool xok1 = (x1 >= 0) && (x1 < W_);
            if (yok0 && xok0) v00 = gtb[y0 * W_ + x0];
            if (yok0 && xok1) v01 = gtb[y0 * W_ + x1];
            if (yok1 && xok0) v10 = gtb[y1 * W_ + x0];
            if (yok1 && xok1) v11 = gtb[y1 * W_ + x1];
            float val = wy0 * wx0 * v00 + wy0 * wx1 * v01
                      + wy1 * wx0 * v10 + wy1 * wx1 * v11;

            // scatter (truncation matches astype(int32) after the clip)
            float rf = (gy + 1.0f) * 0.5f * (float)H_;
            float cf = (gx + 1.0f) * 0.5f * (float)W_;
            int rI = (int)rf;  rI = rI < 0 ? 0 : (rI > H_ - 1 ? H_ - 1 : rI);
            int cI = (int)cf;  cI = cI < 0 ? 0 : (cI > W_ - 1 ? W_ - 1 : cI);
            if (rI >= 96) out[((size_t)b * H_ + rI) * W_ + cI] = val;
        }
    } else if (bid < NR1 + NR2) {
        // ================= role 2: transpose 4 rows ========================
        int idx = bid - NR1;
        int b  = idx >> 6;        // 0..31
        int c4 = idx & 63;        // 4-row chunk 0..63
        int r0 = 4 * c4;
        // rows are contiguous: c0[k] for k in [0,1216) spans 4 rows x 304.
        const float4* c0 = dvf4 + (((size_t)(b * 2 + 0) * H_) + r0) * 304;
        const float4* c1 = dvf4 + (((size_t)(b * 2 + 1) * H_) + r0) * 304;
        float4* dst = reinterpret_cast<float4*>(out + OUT_DVT_OFF)
                      + (((size_t)b * H_) + r0) * 608;
        int k = t;
#pragma unroll
        for (int rep = 0; rep < 2; rep++) {   // 2 reps x 2-wide = 4 iters
            float4 a0 = c0[k];         float4 q0 = c1[k];
            float4 a1 = c0[k + 256];   float4 q1 = c1[k + 256];
            __stcs(&dst[2 * k + 0],           make_float4(a0.x, q0.x, a0.y, q0.y));
            __stcs(&dst[2 * k + 1],           make_float4(a0.z, q0.z, a0.w, q0.w));
            __stcs(&dst[2 * (k + 256) + 0],   make_float4(a1.x, q1.x, a1.y, q1.y));
            __stcs(&dst[2 * (k + 256) + 1],   make_float4(a1.z, q1.z, a1.w, q1.w));
            k += 512;
        }
        // remainder: k = t + 1024, tasks 1216 => threads t<192 do one more
        if (k < 1216) {
            float4 a0 = c0[k];  float4 q0 = c1[k];
            __stcs(&dst[2 * k + 0], make_float4(a0.x, q0.x, a0.y, q0.y));
            __stcs(&dst[2 * k + 1], make_float4(a0.z, q0.z, a0.w, q0.w));
        }
    } else {
        // ================= role 3: zero complementary rows =================
        int idx = bid - NR1 - NR2;
        int b = idx >> 4;
        int i = idx & 15;
        const float4 zero4 = make_float4(0.f, 0.f, 0.f, 0.f);
        // rows [16i, 16i+4)
        float4* z0 = reinterpret_cast<float4*>(out)
                     + (((size_t)b * H_) + 16 * i) * 304;
        // rows [16i+12, 16i+16)
        float4* z1 = reinterpret_cast<float4*>(out)
                     + (((size_t)b * H_) + 16 * i + 12) * 304;
#pragma unroll 1
        for (int k = t; k < 4 * 304; k += 256) {
            __stcs(&z0[k], zero4);
            __stcs(&z1[k], zero4);
        }
    }
}

// ---------------------------------------------------------------------------
extern "C" void kernel_launch(void* const* d_in, const int* in_sizes, int n_in,
                              void* d_out, int out_size) {
    const float* gt  = (const float*)d_in[0];
    const float* dvf = (const float*)d_in[1];
    float* out = (float*)d_out;

    // Gaussian weights in double, normalized per-axis (separable equivalent of
    // k = outer(gh,gw)/k.sum()).
    K30 GH; K49 GW;
    {
        double sh = (2.0 * (double)H_ / (double)(SH_ + 1)) / 3.0;  // 512/17/3
        double sw = (2.0 * (double)W_ / (double)(SW_ + 1)) / 3.0;  // 2432/49/3
        double g[KW_], s;
        s = 0.0;
        for (int r = 0; r < KH_; r++) {
            double u = ((double)r - (double)(KH_ - 1) / 2.0) / sh;
            g[r] = exp(-u * u / 2.0);
            s += g[r];
        }
        for (int r = 0; r < KH_; r++) GH.v[r] = (float)(g[r] / s);
        s = 0.0;
        for (int c = 0; c < KW_; c++) {
            double u = ((double)c - (double)(KW_ - 1) / 2.0) / sw;
            g[c] = exp(-u * u / 2.0);
            s += g[c];
        }
        for (int c = 0; c < KW_; c++) GW.v[c] = (float)(g[c] / s);
    }

    k_mega<<<GRID_TOTAL, 256>>>((const float4*)dvf, gt, out, GH, GW);
}